// round 1
// baseline (speedup 1.0000x reference)
#include <cuda_runtime.h>
#include <cstdint>
#include <cstddef>

// Problem constants
#define BB   32
#define CC   256
#define HH   56
#define WW   56
#define HWSZ 3136          // 56*56
#define GG   4
#define KS   7
#define KK2  49            // 7*7
#define CRR  64            // C / 4

typedef unsigned long long ull;

// Scratch (device globals: allocation-free per harness rules)
__device__ float g_scratch[(size_t)BB * CC * HWSZ];   // gelu(dwconv(s)) : ~103 MB
__device__ float g_pooled[BB * CC];
__device__ float g_wk[(size_t)BB * CC * KK2];         // per-(b,c) 7x7 kernels

// ---------------------------------------------------------------------------
// helpers
// ---------------------------------------------------------------------------
__device__ __forceinline__ float gelu_f(float x) {
    // exact GELU: x * 0.5 * (1 + erf(x / sqrt(2)))
    return 0.5f * x * (1.0f + erff(x * 0.70710678118654752440f));
}

__device__ __forceinline__ ull pack2(float lo, float hi) {
    ull r; asm("mov.b64 %0, {%1, %2};" : "=l"(r) : "f"(lo), "f"(hi)); return r;
}
__device__ __forceinline__ void fma2(ull& d, ull a, ull b) {
    // packed fp32x2 FMA (Blackwell): 2x fp32 pipe throughput vs FFMA
    asm("fma.rn.f32x2 %0, %1, %2, %0;" : "+l"(d) : "l"(a), "l"(b));
}
__device__ __forceinline__ float2 unpack2(ull v) {
    float2 r; asm("mov.b64 {%0, %1}, %2;" : "=f"(r.x), "=f"(r.y) : "l"(v)); return r;
}

// ---------------------------------------------------------------------------
// Kernel 1: pooled[b,c] = mean over H,W of r
// grid = B*C blocks, 256 threads
// ---------------------------------------------------------------------------
__global__ void pool_kernel(const float* __restrict__ r) {
    const int bc = blockIdx.x;
    const float4* p = reinterpret_cast<const float4*>(r + (size_t)bc * HWSZ);
    float s = 0.f;
    for (int i = threadIdx.x; i < HWSZ / 4; i += blockDim.x) {
        float4 v = p[i];
        s += v.x + v.y + v.z + v.w;
    }
    __shared__ float red[8];
    #pragma unroll
    for (int o = 16; o > 0; o >>= 1) s += __shfl_down_sync(0xFFFFFFFFu, s, o);
    if ((threadIdx.x & 31) == 0) red[threadIdx.x >> 5] = s;
    __syncthreads();
    if (threadIdx.x < 8) {
        s = red[threadIdx.x];
        #pragma unroll
        for (int o = 4; o > 0; o >>= 1) s += __shfl_down_sync(0xFFu, s, o);
        if (threadIdx.x == 0) g_pooled[bc] = s * (1.0f / (float)HWSZ);
    }
}

// ---------------------------------------------------------------------------
// Kernel 2: SE weight generation -> g_wk[b,c,49]
// grid = B blocks, 256 threads (thread == channel c)
// ---------------------------------------------------------------------------
__global__ void wgen_kernel(const float* __restrict__ w1, const float* __restrict__ b1,
                            const float* __restrict__ w2, const float* __restrict__ b2,
                            const float* __restrict__ weight, const float* __restrict__ bscale) {
    const int b = blockIdx.x;
    const int t = threadIdx.x;
    __shared__ float ps[CC];
    __shared__ float hs[CRR];

    ps[t] = g_pooled[b * CC + t];
    __syncthreads();

    if (t < CRR) {
        float acc = b1[t];
        const float* wr = w1 + (size_t)t * CC;
        #pragma unroll 4
        for (int c = 0; c < CC; c++) acc = fmaf(ps[c], wr[c], acc);
        hs[t] = gelu_f(acc);
    }
    __syncthreads();

    float vals[GG][2];
    #pragma unroll
    for (int g = 0; g < GG; g++) {
        #pragma unroll
        for (int e = 0; e < 2; e++) {
            const int row = (g * CC + t) * 2 + e;
            float acc = b2[row];
            const float* wr = w2 + (size_t)row * CRR;
            #pragma unroll 4
            for (int k = 0; k < CRR; k++) acc = fmaf(hs[k], wr[k], acc);
            vals[g][e] = acc;
        }
    }

    // softmax over groups (stable), beta = tanh(0.1 * exp(beta_scale) * v1)
    float m = fmaxf(fmaxf(vals[0][0], vals[1][0]), fmaxf(vals[2][0], vals[3][0]));
    float alpha[GG];
    float ssum = 0.f;
    #pragma unroll
    for (int g = 0; g < GG; g++) { alpha[g] = expf(vals[g][0] - m); ssum += alpha[g]; }
    const float inv = 1.0f / ssum;
    float betasum = 0.f;
    #pragma unroll
    for (int g = 0; g < GG; g++) {
        alpha[g] *= inv;
        betasum += tanhf(vals[g][1] * expf(bscale[g * CC + t]) * 0.1f);
    }

    float* out = g_wk + ((size_t)b * CC + t) * KK2;
    #pragma unroll
    for (int k = 0; k < KK2; k++) {
        float acc = betasum;
        #pragma unroll
        for (int g = 0; g < GG; g++)
            acc = fmaf(alpha[g], weight[((size_t)g * CC + t) * KK2 + k], acc);
        out[k] = acc;
    }
}

// ---------------------------------------------------------------------------
// Kernel 3: dynamic depthwise 7x7 conv (pad 3) + exact GELU -> g_scratch
// grid = B*C blocks (one 56x56 plane each), 256 threads
// Each thread computes 1x4 output strips with an sliding smem window.
// ---------------------------------------------------------------------------
__global__ void __launch_bounds__(256) dw_kernel(const float* __restrict__ s) {
    const int bc = blockIdx.x;
    const float* plane = s + (size_t)bc * HWSZ;
    __shared__ __align__(16) float sm[62 * 64];   // padded plane, row stride 64
    __shared__ float wsh[KK2];
    const int t = threadIdx.x;

    if (t < KK2) wsh[t] = g_wk[(size_t)bc * KK2 + t];
    for (int i = t; i < 62 * 62; i += 256) {
        const int yy = i / 62, xx = i % 62;
        const int y = yy - 3, x = xx - 3;
        float v = 0.f;
        if ((unsigned)y < 56u && (unsigned)x < 56u) v = plane[y * WW + x];
        sm[yy * 64 + xx] = v;
    }
    __syncthreads();

    float wr[KK2];
    #pragma unroll
    for (int k = 0; k < KK2; k++) wr[k] = wsh[k];

    float* out = g_scratch + (size_t)bc * HWSZ;
    for (int i = t; i < HWSZ / 4; i += 256) {
        const int y = i / 14;
        const int x0 = (i % 14) * 4;
        float acc0 = 0.f, acc1 = 0.f, acc2 = 0.f, acc3 = 0.f;
        #pragma unroll
        for (int ky = 0; ky < KS; ky++) {
            const float* row = &sm[(y + ky) * 64 + x0];
            const float4 a = *reinterpret_cast<const float4*>(row);
            const float4 bq = *reinterpret_cast<const float4*>(row + 4);
            const float4 cq = *reinterpret_cast<const float4*>(row + 8);
            const float win[12] = {a.x, a.y, a.z, a.w, bq.x, bq.y, bq.z, bq.w,
                                   cq.x, cq.y, cq.z, cq.w};
            #pragma unroll
            for (int kx = 0; kx < KS; kx++) {
                const float w = wr[ky * KS + kx];
                acc0 = fmaf(w, win[kx + 0], acc0);
                acc1 = fmaf(w, win[kx + 1], acc1);
                acc2 = fmaf(w, win[kx + 2], acc2);
                acc3 = fmaf(w, win[kx + 3], acc3);
            }
        }
        float4 o;
        o.x = gelu_f(acc0); o.y = gelu_f(acc1); o.z = gelu_f(acc2); o.w = gelu_f(acc3);
        *reinterpret_cast<float4*>(out + y * WW + x0) = o;
    }
}

// ---------------------------------------------------------------------------
// Kernel 4: pointwise conv  out[b,d,p] = sum_c pw_w[d,c] * t[b,c,p] + pw_b[d]
// Tiled SGEMM: 128(d) x 128(p) block tile, 8x8 per thread, K-step 8,
// double-buffered smem, packed fp32x2 FMA in the inner product.
// grid = (ceil(HW/128)=25, C/128=2, B=32), 256 threads
// ---------------------------------------------------------------------------
__global__ void __launch_bounds__(256, 2) pw_gemm_kernel(const float* __restrict__ A,
                                                         const float* __restrict__ bias,
                                                         float* __restrict__ out) {
    __shared__ __align__(16) float As[2][8][128];
    __shared__ __align__(16) float Bs[2][8][128];

    const int t = threadIdx.x;
    const int b = blockIdx.z;
    const int dBase = blockIdx.y * 128;
    const int p0 = blockIdx.x * 128;
    const float* __restrict__ Bg = g_scratch + (size_t)b * CC * HWSZ;

    // global-load assignments
    const int a_d = t >> 1;             // 0..127
    const int a_k = (t & 1) * 4;        // 0 or 4
    const int b_c = t >> 5;             // 0..7
    const int b_p = (t & 31) * 4;       // 0..124
    const bool bvalid = (p0 + b_p) < HWSZ;

    // prologue: tile 0
    {
        float4 av = *reinterpret_cast<const float4*>(A + (size_t)(dBase + a_d) * CC + a_k);
        float4 bv = make_float4(0.f, 0.f, 0.f, 0.f);
        if (bvalid) bv = *reinterpret_cast<const float4*>(Bg + (size_t)b_c * HWSZ + p0 + b_p);
        As[0][a_k + 0][a_d] = av.x;
        As[0][a_k + 1][a_d] = av.y;
        As[0][a_k + 2][a_d] = av.z;
        As[0][a_k + 3][a_d] = av.w;
        *reinterpret_cast<float4*>(&Bs[0][b_c][b_p]) = bv;
    }

    ull acc[8][4];
    #pragma unroll
    for (int i = 0; i < 8; i++)
        #pragma unroll
        for (int j = 0; j < 4; j++) acc[i][j] = 0ull;

    const int tx = t & 15;   // p sub-tile
    const int ty = t >> 4;   // d sub-tile

    const int NKT = CC / 8;  // 32 k-tiles
    for (int kt = 0; kt < NKT; kt++) {
        __syncthreads();
        const int cur = kt & 1;

        float4 av2, bv2;
        const bool more = (kt + 1) < NKT;
        if (more) {
            const int k0 = (kt + 1) * 8;
            av2 = *reinterpret_cast<const float4*>(A + (size_t)(dBase + a_d) * CC + k0 + a_k);
            bv2 = make_float4(0.f, 0.f, 0.f, 0.f);
            if (bvalid)
                bv2 = *reinterpret_cast<const float4*>(Bg + (size_t)(k0 + b_c) * HWSZ + p0 + b_p);
        }

        #pragma unroll
        for (int k = 0; k < 8; k++) {
            const float4 aq0 = *reinterpret_cast<const float4*>(&As[cur][k][ty * 8]);
            const float4 aq1 = *reinterpret_cast<const float4*>(&As[cur][k][ty * 8 + 4]);
            const float4 bq0 = *reinterpret_cast<const float4*>(&Bs[cur][k][tx * 8]);
            const float4 bq1 = *reinterpret_cast<const float4*>(&Bs[cur][k][tx * 8 + 4]);

            ull bp[4];
            bp[0] = pack2(bq0.x, bq0.y);
            bp[1] = pack2(bq0.z, bq0.w);
            bp[2] = pack2(bq1.x, bq1.y);
            bp[3] = pack2(bq1.z, bq1.w);

            const float aa[8] = {aq0.x, aq0.y, aq0.z, aq0.w, aq1.x, aq1.y, aq1.z, aq1.w};
            #pragma unroll
            for (int i = 0; i < 8; i++) {
                const ull ap = pack2(aa[i], aa[i]);
                fma2(acc[i][0], ap, bp[0]);
                fma2(acc[i][1], ap, bp[1]);
                fma2(acc[i][2], ap, bp[2]);
                fma2(acc[i][3], ap, bp[3]);
            }
        }

        if (more) {
            const int nxt = 1 - cur;
            As[nxt][a_k + 0][a_d] = av2.x;
            As[nxt][a_k + 1][a_d] = av2.y;
            As[nxt][a_k + 2][a_d] = av2.z;
            As[nxt][a_k + 3][a_d] = av2.w;
            *reinterpret_cast<float4*>(&Bs[nxt][b_c][b_p]) = bv2;
        }
    }

    // epilogue: add bias, store
    #pragma unroll
    for (int i = 0; i < 8; i++) {
        const int d = dBase + ty * 8 + i;
        const float bb = bias[d];
        float* orow = out + ((size_t)b * CC + d) * HWSZ;
        #pragma unroll
        for (int j2 = 0; j2 < 4; j2++) {
            const int p = p0 + tx * 8 + j2 * 2;
            if (p < HWSZ) {
                float2 v = unpack2(acc[i][j2]);
                v.x += bb;
                v.y += bb;
                *reinterpret_cast<float2*>(orow + p) = v;
            }
        }
    }
}

// ---------------------------------------------------------------------------
// launch
// inputs (metadata order): s, r, proj_w1, proj_b1, proj_w2, proj_b2,
//                          weight, beta_scale, pw_w, pw_b
// ---------------------------------------------------------------------------
extern "C" void kernel_launch(void* const* d_in, const int* in_sizes, int n_in,
                              void* d_out, int out_size) {
    (void)in_sizes; (void)n_in; (void)out_size;
    const float* s      = (const float*)d_in[0];
    const float* r      = (const float*)d_in[1];
    const float* pw1    = (const float*)d_in[2];
    const float* pb1    = (const float*)d_in[3];
    const float* pw2    = (const float*)d_in[4];
    const float* pb2    = (const float*)d_in[5];
    const float* weight = (const float*)d_in[6];
    const float* bscale = (const float*)d_in[7];
    const float* pww    = (const float*)d_in[8];
    const float* pwb    = (const float*)d_in[9];
    float* out = (float*)d_out;

    pool_kernel<<<BB * CC, 256>>>(r);
    wgen_kernel<<<BB, 256>>>(pw1, pb1, pw2, pb2, weight, bscale);
    dw_kernel<<<BB * CC, 256>>>(s);
    dim3 grid((HWSZ + 127) / 128, CC / 128, BB);
    pw_gemm_kernel<<<grid, 256>>>(pww, pwb, out);
}

// round 2
// speedup vs baseline: 1.2475x; 1.2475x over previous
#include <cuda_runtime.h>
#include <cstdint>
#include <cstddef>

// Problem constants
#define BB   32
#define CC   256
#define HH   56
#define WW   56
#define HWSZ 3136          // 56*56
#define GG   4
#define KS   7
#define KK2  49            // 7*7
#define CRR  64            // C / 4
#define NTOT (BB * HWSZ)   // 100352 = 392 * 256

typedef unsigned long long ull;

// Scratch (device globals: allocation-free per harness rules)
__device__ float g_scratch[(size_t)BB * CC * HWSZ];   // gelu(dwconv(s)) : ~103 MB
__device__ float g_pooled[BB * CC];
__device__ float g_wk[(size_t)BB * CC * KK2];         // per-(b,c) 7x7 kernels

// ---------------------------------------------------------------------------
// helpers
// ---------------------------------------------------------------------------
__device__ __forceinline__ float gelu_f(float x) {
    return 0.5f * x * (1.0f + erff(x * 0.70710678118654752440f));
}
__device__ __forceinline__ ull pack2(float lo, float hi) {
    ull r; asm("mov.b64 %0, {%1, %2};" : "=l"(r) : "f"(lo), "f"(hi)); return r;
}
__device__ __forceinline__ void fma2(ull& d, ull a, ull b) {
    asm("fma.rn.f32x2 %0, %1, %2, %0;" : "+l"(d) : "l"(a), "l"(b));
}
__device__ __forceinline__ float2 unpack2(ull v) {
    float2 r; asm("mov.b64 {%0, %1}, %2;" : "=f"(r.x), "=f"(r.y) : "l"(v)); return r;
}

// ---------------------------------------------------------------------------
// Kernel 1: pooled[b,c] = mean over H,W of r
// ---------------------------------------------------------------------------
__global__ void pool_kernel(const float* __restrict__ r) {
    const int bc = blockIdx.x;
    const float4* p = reinterpret_cast<const float4*>(r + (size_t)bc * HWSZ);
    float s = 0.f;
    for (int i = threadIdx.x; i < HWSZ / 4; i += blockDim.x) {
        float4 v = p[i];
        s += v.x + v.y + v.z + v.w;
    }
    __shared__ float red[8];
    #pragma unroll
    for (int o = 16; o > 0; o >>= 1) s += __shfl_down_sync(0xFFFFFFFFu, s, o);
    if ((threadIdx.x & 31) == 0) red[threadIdx.x >> 5] = s;
    __syncthreads();
    if (threadIdx.x < 8) {
        s = red[threadIdx.x];
        #pragma unroll
        for (int o = 4; o > 0; o >>= 1) s += __shfl_down_sync(0xFFu, s, o);
        if (threadIdx.x == 0) g_pooled[bc] = s * (1.0f / (float)HWSZ);
    }
}

// ---------------------------------------------------------------------------
// Kernel 2: SE weight generation -> g_wk[b,c,49]
// ---------------------------------------------------------------------------
__global__ void wgen_kernel(const float* __restrict__ w1, const float* __restrict__ b1,
                            const float* __restrict__ w2, const float* __restrict__ b2,
                            const float* __restrict__ weight, const float* __restrict__ bscale) {
    const int b = blockIdx.x;
    const int t = threadIdx.x;
    __shared__ float ps[CC];
    __shared__ float hs[CRR];

    ps[t] = g_pooled[b * CC + t];
    __syncthreads();

    if (t < CRR) {
        float acc = b1[t];
        const float* wr = w1 + (size_t)t * CC;
        #pragma unroll 4
        for (int c = 0; c < CC; c++) acc = fmaf(ps[c], wr[c], acc);
        hs[t] = gelu_f(acc);
    }
    __syncthreads();

    float vals[GG][2];
    #pragma unroll
    for (int g = 0; g < GG; g++) {
        #pragma unroll
        for (int e = 0; e < 2; e++) {
            const int row = (g * CC + t) * 2 + e;
            float acc = b2[row];
            const float* wr = w2 + (size_t)row * CRR;
            #pragma unroll 4
            for (int k = 0; k < CRR; k++) acc = fmaf(hs[k], wr[k], acc);
            vals[g][e] = acc;
        }
    }

    float m = fmaxf(fmaxf(vals[0][0], vals[1][0]), fmaxf(vals[2][0], vals[3][0]));
    float alpha[GG];
    float ssum = 0.f;
    #pragma unroll
    for (int g = 0; g < GG; g++) { alpha[g] = expf(vals[g][0] - m); ssum += alpha[g]; }
    const float inv = 1.0f / ssum;
    float betasum = 0.f;
    #pragma unroll
    for (int g = 0; g < GG; g++) {
        alpha[g] *= inv;
        betasum += tanhf(vals[g][1] * expf(bscale[g * CC + t]) * 0.1f);
    }

    float* out = g_wk + ((size_t)b * CC + t) * KK2;
    #pragma unroll
    for (int k = 0; k < KK2; k++) {
        float acc = betasum;
        #pragma unroll
        for (int g = 0; g < GG; g++)
            acc = fmaf(alpha[g], weight[((size_t)g * CC + t) * KK2 + k], acc);
        out[k] = acc;
    }
}

// ---------------------------------------------------------------------------
// Kernel 3: dynamic depthwise 7x7 conv (pad 3) + exact GELU -> g_scratch
// 2 planes per 256-thread block; half-block (128 thr) per plane.
// Each thread computes 4x4 output tiles with packed f32x2 FMA.
// ---------------------------------------------------------------------------
__global__ void __launch_bounds__(256, 2) dw_kernel(const float* __restrict__ s) {
    const int bc0 = blockIdx.x * 2;
    __shared__ __align__(16) float sm[2][62 * 64];   // padded planes, row stride 64
    const int t = threadIdx.x;

    // cooperative load of both planes (zero-padded borders)
    for (int i = t; i < 2 * 62 * 62; i += 256) {
        const int pl = i / 3844;
        const int j = i - pl * 3844;
        const int yy = j / 62, xx = j - yy * 62;
        const int y = yy - 3, x = xx - 3;
        float v = 0.f;
        if ((unsigned)y < 56u && (unsigned)x < 56u)
            v = s[(size_t)(bc0 + pl) * HWSZ + y * WW + x];
        sm[pl][yy * 64 + xx] = v;
    }

    const int plane = t >> 7;
    const int tid = t & 127;
    const int bc = bc0 + plane;

    float wr[KK2];
    {
        const float* wsrc = g_wk + (size_t)bc * KK2;
        #pragma unroll
        for (int k = 0; k < KK2; k++) wr[k] = wsrc[k];
    }
    __syncthreads();

    float* out = g_scratch + (size_t)bc * HWSZ;
    const float* smp = sm[plane];

    // 196 4x4 tiles per plane (14 x 14)
    #pragma unroll 1
    for (int j = tid; j < 196; j += 128) {
        const int ty4 = j / 14;
        const int tx4 = j - ty4 * 14;
        const int y0 = ty4 * 4;
        const int x0 = tx4 * 4;

        ull acc[4][2];
        #pragma unroll
        for (int oy = 0; oy < 4; oy++) { acc[oy][0] = 0ull; acc[oy][1] = 0ull; }

        #pragma unroll
        for (int r = 0; r < 10; r++) {
            const float* row = &smp[(y0 + r) * 64 + x0];
            const float4 qa = *reinterpret_cast<const float4*>(row);
            const float4 qb = *reinterpret_cast<const float4*>(row + 4);
            const float4 qc = *reinterpret_cast<const float4*>(row + 8);
            ull p[9];
            p[0] = pack2(qa.x, qa.y);
            p[1] = pack2(qa.y, qa.z);
            p[2] = pack2(qa.z, qa.w);
            p[3] = pack2(qa.w, qb.x);
            p[4] = pack2(qb.x, qb.y);
            p[5] = pack2(qb.y, qb.z);
            p[6] = pack2(qb.z, qb.w);
            p[7] = pack2(qb.w, qc.x);
            p[8] = pack2(qc.x, qc.y);
            #pragma unroll
            for (int oy = 0; oy < 4; oy++) {
                const int ky = r - oy;
                if (ky >= 0 && ky < 7) {
                    #pragma unroll
                    for (int kx = 0; kx < 7; kx++) {
                        const float w = wr[ky * 7 + kx];
                        const ull wp = pack2(w, w);
                        fma2(acc[oy][0], wp, p[kx]);
                        fma2(acc[oy][1], wp, p[kx + 2]);
                    }
                }
            }
        }

        #pragma unroll
        for (int oy = 0; oy < 4; oy++) {
            const float2 v0 = unpack2(acc[oy][0]);
            const float2 v1 = unpack2(acc[oy][1]);
            float4 o;
            o.x = gelu_f(v0.x); o.y = gelu_f(v0.y);
            o.z = gelu_f(v1.x); o.w = gelu_f(v1.y);
            *reinterpret_cast<float4*>(out + (y0 + oy) * WW + x0) = o;
        }
    }
}

// ---------------------------------------------------------------------------
// Kernel 4: pointwise conv as SGEMM over flattened n = b*3136 + p
// out[d, n] = sum_c pw_w[d,c] * scratch[c, n] + pw_b[d]
// Block tile: 128(d) x 256(n), K-step 8, double-buffered, 8x16 per thread
// with packed f32x2 FMA. grid = (392, 2). Zero tail (100352 = 392*256).
// ---------------------------------------------------------------------------
__global__ void __launch_bounds__(256, 1) pw_gemm_kernel(const float* __restrict__ A,
                                                         const float* __restrict__ bias,
                                                         float* __restrict__ out) {
    __shared__ __align__(16) float As[2][8][128];
    __shared__ __align__(16) float Bs[2][8][256];

    const int t = threadIdx.x;
    const int nbb = blockIdx.x * 256;
    const int dBase = blockIdx.y * 128;

    // global-load assignments
    const int a_d = t >> 1;             // 0..127
    const int a_k = (t & 1) * 4;        // 0 or 4
    const int b_c = t >> 5;             // 0..7
    const int b_o = (t & 31) * 4;       // 0..124

    // precompute the two B-load base pointers (n -> (b, p) mapping)
    const int n_a = nbb + b_o;
    const int n_b = n_a + 128;
    const int ba = n_a / HWSZ;
    const int bbx = n_b / HWSZ;
    const float* __restrict__ Bga = g_scratch + (size_t)ba * CC * HWSZ + (n_a - ba * HWSZ);
    const float* __restrict__ Bgb = g_scratch + (size_t)bbx * CC * HWSZ + (n_b - bbx * HWSZ);
    const float* __restrict__ Ag = A + (size_t)(dBase + a_d) * CC + a_k;

    // prologue: tile 0
    {
        const float4 av = *reinterpret_cast<const float4*>(Ag);
        const float4 bv0 = *reinterpret_cast<const float4*>(Bga + (size_t)b_c * HWSZ);
        const float4 bv1 = *reinterpret_cast<const float4*>(Bgb + (size_t)b_c * HWSZ);
        As[0][a_k + 0][a_d] = av.x;
        As[0][a_k + 1][a_d] = av.y;
        As[0][a_k + 2][a_d] = av.z;
        As[0][a_k + 3][a_d] = av.w;
        *reinterpret_cast<float4*>(&Bs[0][b_c][b_o]) = bv0;
        *reinterpret_cast<float4*>(&Bs[0][b_c][b_o + 128]) = bv1;
    }

    ull acc[8][8];
    #pragma unroll
    for (int i = 0; i < 8; i++)
        #pragma unroll
        for (int j = 0; j < 8; j++) acc[i][j] = 0ull;

    const int tx = t & 15;   // n sub-tile: 4 disjoint 64-wide segments
    const int ty = t >> 4;   // d sub-tile

    const int NKT = CC / 8;  // 32 k-tiles
    for (int kt = 0; kt < NKT; kt++) {
        __syncthreads();
        const int cur = kt & 1;

        float4 av2, bv20, bv21;
        const bool more = (kt + 1) < NKT;
        if (more) {
            const int k0 = (kt + 1) * 8;
            av2 = *reinterpret_cast<const float4*>(Ag + k0);
            bv20 = *reinterpret_cast<const float4*>(Bga + (size_t)(k0 + b_c) * HWSZ);
            bv21 = *reinterpret_cast<const float4*>(Bgb + (size_t)(k0 + b_c) * HWSZ);
        }

        #pragma unroll
        for (int k = 0; k < 8; k++) {
            const float4 aq0 = *reinterpret_cast<const float4*>(&As[cur][k][ty * 8]);
            const float4 aq1 = *reinterpret_cast<const float4*>(&As[cur][k][ty * 8 + 4]);
            const float4 b0 = *reinterpret_cast<const float4*>(&Bs[cur][k][tx * 4]);
            const float4 b1 = *reinterpret_cast<const float4*>(&Bs[cur][k][tx * 4 + 64]);
            const float4 b2 = *reinterpret_cast<const float4*>(&Bs[cur][k][tx * 4 + 128]);
            const float4 b3 = *reinterpret_cast<const float4*>(&Bs[cur][k][tx * 4 + 192]);

            ull bp[8];
            bp[0] = pack2(b0.x, b0.y);
            bp[1] = pack2(b0.z, b0.w);
            bp[2] = pack2(b1.x, b1.y);
            bp[3] = pack2(b1.z, b1.w);
            bp[4] = pack2(b2.x, b2.y);
            bp[5] = pack2(b2.z, b2.w);
            bp[6] = pack2(b3.x, b3.y);
            bp[7] = pack2(b3.z, b3.w);

            const float aa[8] = {aq0.x, aq0.y, aq0.z, aq0.w, aq1.x, aq1.y, aq1.z, aq1.w};
            #pragma unroll
            for (int i = 0; i < 8; i++) {
                const ull ap = pack2(aa[i], aa[i]);
                #pragma unroll
                for (int j = 0; j < 8; j++) fma2(acc[i][j], ap, bp[j]);
            }
        }

        if (more) {
            const int nxt = 1 - cur;
            As[nxt][a_k + 0][a_d] = av2.x;
            As[nxt][a_k + 1][a_d] = av2.y;
            As[nxt][a_k + 2][a_d] = av2.z;
            As[nxt][a_k + 3][a_d] = av2.w;
            *reinterpret_cast<float4*>(&Bs[nxt][b_c][b_o]) = bv20;
            *reinterpret_cast<float4*>(&Bs[nxt][b_c][b_o + 128]) = bv21;
        }
    }

    // epilogue: add bias, store (each 64-wide segment lies within one batch b
    // since 64 | 3136)
    #pragma unroll
    for (int q = 0; q < 4; q++) {
        const int n0 = nbb + q * 64 + tx * 4;
        const int bq = n0 / HWSZ;
        const int pq = n0 - bq * HWSZ;
        #pragma unroll
        for (int i = 0; i < 8; i++) {
            const int d = dBase + ty * 8 + i;
            const float bb = bias[d];
            float2 v0 = unpack2(acc[i][q * 2]);
            float2 v1 = unpack2(acc[i][q * 2 + 1]);
            float4 o;
            o.x = v0.x + bb; o.y = v0.y + bb; o.z = v1.x + bb; o.w = v1.y + bb;
            *reinterpret_cast<float4*>(out + ((size_t)bq * CC + d) * HWSZ + pq) = o;
        }
    }
}

// ---------------------------------------------------------------------------
// launch
// ---------------------------------------------------------------------------
extern "C" void kernel_launch(void* const* d_in, const int* in_sizes, int n_in,
                              void* d_out, int out_size) {
    (void)in_sizes; (void)n_in; (void)out_size;
    const float* s      = (const float*)d_in[0];
    const float* r      = (const float*)d_in[1];
    const float* pw1    = (const float*)d_in[2];
    const float* pb1    = (const float*)d_in[3];
    const float* pw2    = (const float*)d_in[4];
    const float* pb2    = (const float*)d_in[5];
    const float* weight = (const float*)d_in[6];
    const float* bscale = (const float*)d_in[7];
    const float* pww    = (const float*)d_in[8];
    const float* pwb    = (const float*)d_in[9];
    float* out = (float*)d_out;

    pool_kernel<<<BB * CC, 256>>>(r);
    wgen_kernel<<<BB, 256>>>(pw1, pb1, pw2, pb2, weight, bscale);
    dw_kernel<<<BB * CC / 2, 256>>>(s);
    dim3 grid(NTOT / 256, CC / 128, 1);
    pw_gemm_kernel<<<grid, 256>>>(pww, pwb, out);
}